// round 11
// baseline (speedup 1.0000x reference)
#include <cuda_runtime.h>
#include <math.h>
#include <stdint.h>

#define NB   32
#define CC   256
#define C4   64
#define LL   6
#define TT   64
#define VV   25
#define EPS  1e-5f
#define SLOPE 0.2f
#define NPAIR 45

#define GRID     148
#define NTHREADS 256
#define NTILES   (NB * CC * LL)          // 49152
#define NWARPS_G (GRID * 8)              // 1184
#define OUT_F4   (NB * CC * 400)         // 3276800 float4 outputs
#define DSMEM_BYTES 51200                // 8 warps * 400 float4

// scratch (no cudaMalloc allowed)
__device__ float g_xt[NB * CC * LL * VV];     // [n][c][l][v]
__device__ float g_s[NB * C4 * LL];           // [n][o][l]
__device__ float g_gate[NB * CC * LL];        // [n][c][l]

// self-resetting grid barrier state (zero-init; g_go flips each use,
// g_cnt returns to 0 -> consistent across graph replays)
__device__ int g_cnt[4];
__device__ volatile int g_go[4];

__constant__ int c_pv[NPAIR] = {
    1,0,20,
    0,20,12,16,2,4,8,
    12,16,2,4,8,13,17,3,5,9,
    13,17,3,5,9,14,18,6,10,
    14,18,6,10,15,19,7,11,
    15,19,7,11,21,22,23,24};
__constant__ int c_off[LL + 1] = {0,3,10,20,29,37,45};
__constant__ float c_inv_cnt[LL] = {1.f/3.f, 1.f/7.f, 1.f/10.f, 1.f/9.f, 1.f/8.f, 1.f/8.f};

__device__ __forceinline__ void cp_async16(void* dst_smem, const void* src) {
    uint32_t d = (uint32_t)__cvta_generic_to_shared(dst_smem);
    asm volatile("cp.async.cg.shared.global [%0], [%1], 16;\n" :: "r"(d), "l"(src));
}
__device__ __forceinline__ void cp_wait_all() {
    asm volatile("cp.async.wait_all;\n" ::: "memory");
}

__device__ __forceinline__ void grid_barrier(int i) {
    __syncthreads();
    if (threadIdx.x == 0) {
        __threadfence();                      // publish this block's stores
        const int sense = g_go[i];            // read BEFORE arriving (safe)
        const int a = atomicAdd(&g_cnt[i], 1);
        if (a == GRID - 1) {
            g_cnt[i] = 0;
            __threadfence();
            g_go[i] = 1 - sense;
        } else {
            while (g_go[i] == sense) { __nanosleep(64); }
            __threadfence();                  // acquire peers' stores
        }
    }
    __syncthreads();
}

// ---------------------------------------------------------------------------
// Single persistent kernel: all phases, 3 grid barriers, zero launch gaps.
// ---------------------------------------------------------------------------
__global__ __launch_bounds__(NTHREADS) void k_all(
    const float* __restrict__ x,
    const float* __restrict__ W_down, const float* __restrict__ b_down,
    const float* __restrict__ g_down, const float* __restrict__ be_down,
    const float* __restrict__ m_down, const float* __restrict__ v_down,
    const float* __restrict__ W_edge, const float* __restrict__ g_edge,
    const float* __restrict__ be_edge, const float* __restrict__ m_edge,
    const float* __restrict__ v_edge, const float* __restrict__ W_agg,
    const float* __restrict__ b_agg, float* __restrict__ out) {
    extern __shared__ float sm[];
    const int t = threadIdx.x;
    const int wid = t >> 5;
    const int lane = t & 31;
    const int o = t & 63;
    const int g = t >> 6;

    __shared__ float sh_s[C4][LL];
    __shared__ float sh_G[LL * LL];
    __shared__ int   sh_idx[LL][3];
    __shared__ float sh_e[C4][LL];

    // ==== Phase 1: T-max, warp-granular (one warp per tile) ====
    {
        float4* wbuf = reinterpret_cast<float4*>(sm) + wid * 400;
        const float4* x4 = reinterpret_cast<const float4*>(x);
        for (int tile = blockIdx.x * 8 + wid; tile < NTILES; tile += NWARPS_G) {
            const float4* src = x4 + (size_t)tile * 400;
            #pragma unroll
            for (int j = 0; j < 12; j++)
                cp_async16(&wbuf[lane + j * 32], src + lane + j * 32);
            if (lane < 16)
                cp_async16(&wbuf[384 + lane], src + 384 + lane);
            cp_wait_all();
            __syncwarp();
            if (lane < VV) {
                const float* tf = reinterpret_cast<const float*>(wbuf);
                float m0 = tf[lane], m1 = tf[VV + lane];
                float m2 = tf[2 * VV + lane], m3 = tf[3 * VV + lane];
                #pragma unroll
                for (int tt = 4; tt < TT; tt += 4) {
                    m0 = fmaxf(m0, tf[tt * VV + lane]);
                    m1 = fmaxf(m1, tf[(tt + 1) * VV + lane]);
                    m2 = fmaxf(m2, tf[(tt + 2) * VV + lane]);
                    m3 = fmaxf(m3, tf[(tt + 3) * VV + lane]);
                }
                g_xt[(size_t)tile * VV + lane] = fmaxf(fmaxf(m0, m1), fmaxf(m2, m3));
            }
            __syncwarp();
        }
    }
    grid_barrier(0);

    // ==== Phase 2a: s[n][o][l] over 192 units, all blocks ====
    {
        float* shX = sm;                      // [10][256]
        // W_down row (o, quarter g) -> registers, once
        float wreg[64];
        {
            const float4* wr = reinterpret_cast<const float4*>(W_down + o * CC + g * 64);
            #pragma unroll
            for (int i = 0; i < 16; i++) {
                const float4 w = wr[i];
                wreg[4*i] = w.x; wreg[4*i+1] = w.y; wreg[4*i+2] = w.z; wreg[4*i+3] = w.w;
            }
        }
        for (int u = blockIdx.x; u < NB * LL; u += GRID) {
            const int n = u / LL, l = u % LL;
            const int p0 = c_off[l];
            const int cnt = c_off[l + 1] - p0;
            const float* xb = g_xt + ((size_t)n * CC * LL + l) * VV;
            __syncthreads();
            for (int i = t; i < cnt * 256; i += 256) {
                const int p = i >> 8, c = i & 255;
                shX[p * 256 + c] = xb[(size_t)c * (LL * VV) + c_pv[p0 + p]];
            }
            __syncthreads();

            float acc[10];
            #pragma unroll
            for (int p = 0; p < 10; p++) acc[p] = 0.f;
            #pragma unroll
            for (int p = 0; p < 10; p++) {
                if (p < cnt) {
                    const float4* xp = reinterpret_cast<const float4*>(shX + p * 256 + g * 64);
                    float a = 0.f;
                    #pragma unroll
                    for (int i = 0; i < 16; i++) {
                        const float4 xv = xp[i];
                        a += wreg[4*i] * xv.x + wreg[4*i+1] * xv.y
                           + wreg[4*i+2] * xv.z + wreg[4*i+3] * xv.w;
                    }
                    acc[p] = a;
                }
            }
            __syncthreads();                  // X reads done -> reuse shX
            float* parts = shX;               // [g][p][o]
            #pragma unroll
            for (int p = 0; p < 10; p++)
                if (p < cnt) parts[(g * 10 + p) * 64 + o] = acc[p];
            __syncthreads();

            if (t < 64) {
                const float gs  = g_down[t] * rsqrtf(v_down[t] + EPS);
                const float shb = be_down[t] - m_down[t] * gs;
                const float bd  = b_down[t];
                float ssum = 0.f;
                #pragma unroll
                for (int p = 0; p < 10; p++) {
                    if (p < cnt) {
                        const float y = (parts[p * 64 + t] + parts[(10 + p) * 64 + t] +
                                         parts[(20 + p) * 64 + t] + parts[(30 + p) * 64 + t]
                                         + bd) * gs + shb;
                        ssum += fmaxf(y, 0.f);
                    }
                }
                g_s[((size_t)n * C4 + t) * LL + l] = ssum * c_inv_cnt[l];
            }
        }
    }
    grid_barrier(1);

    // ==== Phase 2b: knn + EdgeConv + gate, blocks 0..31 ====
    if (blockIdx.x < NB) {
        const int n = blockIdx.x;
        float* shWe = sm;                     // [64][129] padded

        for (int i = t; i < 64 * 32; i += 256) {
            const int r = i >> 5, c4 = i & 31;
            const float4 w = reinterpret_cast<const float4*>(W_edge + r * 128)[c4];
            float* d = &shWe[r * 129 + c4 * 4];
            d[0] = w.x; d[1] = w.y; d[2] = w.z; d[3] = w.w;
        }
        for (int i = t; i < C4 * LL; i += 256)
            sh_s[i / LL][i % LL] = g_s[(size_t)n * C4 * LL + i];
        __syncthreads();

        if (t < LL * LL) {
            const int i = t / LL, j = t % LL;
            float acc = 0.f;
            #pragma unroll 8
            for (int c = 0; c < C4; c++) acc += sh_s[c][i] * sh_s[c][j];
            sh_G[t] = acc;
        }
        __syncthreads();

        if (t < LL) {
            float d[LL];
            bool used[LL];
            const float sqi = sh_G[t * LL + t];
            #pragma unroll
            for (int j = 0; j < LL; j++) {
                d[j] = 2.f * sh_G[t * LL + j] - sqi - sh_G[j * LL + j];
                used[j] = false;
            }
            #pragma unroll
            for (int k = 0; k < 3; k++) {
                float best = -INFINITY; int bi = 0;
                #pragma unroll
                for (int j = 0; j < LL; j++)
                    if (!used[j] && d[j] > best) { best = d[j]; bi = j; }
                used[bi] = true;
                sh_idx[t][k] = bi;
            }
        }
        __syncthreads();

        for (int item = t; item < LL * C4; item += 256) {
            const int oo = item & 63;
            const int l  = item >> 6;
            const float* w1 = &shWe[oo * 129];
            const float* w2 = w1 + 64;
            const int n0 = sh_idx[l][0], n1 = sh_idx[l][1], n2 = sh_idx[l][2];
            float base = 0.f, a0 = 0.f, a1 = 0.f, a2 = 0.f;
            #pragma unroll 8
            for (int c = 0; c < C4; c++) {
                const float w = w1[c];
                base += (w2[c] - w) * sh_s[c][l];
                a0 += w * sh_s[c][n0];
                a1 += w * sh_s[c][n1];
                a2 += w * sh_s[c][n2];
            }
            const float gs  = g_edge[oo] * rsqrtf(v_edge[oo] + EPS);
            const float shb = be_edge[oo] - m_edge[oo] * gs;
            float m = -INFINITY;
            float ys[3] = {a0 + base, a1 + base, a2 + base};
            #pragma unroll
            for (int k = 0; k < 3; k++) {
                float y = ys[k] * gs + shb;
                y = fmaxf(y, 0.f) + SLOPE * fminf(y, 0.f);
                m = fmaxf(m, y);
            }
            sh_e[oo][l] = m;
        }
        __syncthreads();

        {
            const int oc = t;
            float a[LL];
            const float bb = b_agg[oc];
            #pragma unroll
            for (int l = 0; l < LL; l++) a[l] = bb;
            const float4* wr = reinterpret_cast<const float4*>(W_agg + oc * C4);
            #pragma unroll
            for (int i = 0; i < 16; i++) {
                const float4 w = wr[i];
                const int c = 4 * i;
                #pragma unroll
                for (int l = 0; l < LL; l++)
                    a[l] += w.x * sh_e[c][l] + w.y * sh_e[c+1][l]
                          + w.z * sh_e[c+2][l] + w.w * sh_e[c+3][l];
            }
            float* gp = g_gate + ((size_t)n * CC + oc) * LL;
            #pragma unroll
            for (int l = 0; l < LL; l++)
                gp[l] = 1.f / (1.f + expf(-a[l]));
        }
    }
    grid_barrier(2);

    // ==== Phase 3: gated sum over L (grid-stride, float4) ====
    {
        const float4* x4 = reinterpret_cast<const float4*>(x);
        float4* out4 = reinterpret_cast<float4*>(out);
        const int stride = GRID * NTHREADS;
        for (int idx = blockIdx.x * NTHREADS + t; idx < OUT_F4; idx += stride) {
            const int tv4 = idx % 400;
            const int nc  = idx / 400;
            const float4* xb = x4 + (size_t)nc * (LL * 400) + tv4;
            const float* gp = g_gate + (size_t)nc * LL;
            float4 acc = make_float4(0.f, 0.f, 0.f, 0.f);
            #pragma unroll
            for (int l = 0; l < LL; l++) {
                const float gv = gp[l];
                const float4 xv = xb[l * 400];
                acc.x += xv.x * gv; acc.y += xv.y * gv;
                acc.z += xv.z * gv; acc.w += xv.w * gv;
            }
            out4[idx] = acc;
        }
    }
}

// ---------------------------------------------------------------------------
extern "C" void kernel_launch(void* const* d_in, const int* in_sizes, int n_in,
                              void* d_out, int out_size) {
    const float* x       = (const float*)d_in[0];
    const float* W_down  = (const float*)d_in[1];
    const float* b_down  = (const float*)d_in[2];
    const float* g_down  = (const float*)d_in[3];
    const float* be_down = (const float*)d_in[4];
    const float* m_down  = (const float*)d_in[5];
    const float* v_down  = (const float*)d_in[6];
    const float* W_edge  = (const float*)d_in[7];
    const float* g_edge  = (const float*)d_in[8];
    const float* be_edge = (const float*)d_in[9];
    const float* m_edge  = (const float*)d_in[10];
    const float* v_edge  = (const float*)d_in[11];
    const float* W_agg   = (const float*)d_in[12];
    const float* b_agg   = (const float*)d_in[13];
    float* out = (float*)d_out;

    (void)cudaFuncSetAttribute(k_all,
                               cudaFuncAttributeMaxDynamicSharedMemorySize,
                               DSMEM_BYTES);
    k_all<<<GRID, NTHREADS, DSMEM_BYTES>>>(
        x, W_down, b_down, g_down, be_down, m_down, v_down,
        W_edge, g_edge, be_edge, m_edge, v_edge, W_agg, b_agg, out);
}

// round 14
// speedup vs baseline: 1.0534x; 1.0534x over previous
#include <cuda_runtime.h>
#include <math.h>
#include <stdint.h>

#define NB   32
#define CC   256
#define C4   64
#define LL   6
#define TT   64
#define VV   25
#define EPS  1e-5f
#define SLOPE 0.2f
#define NPAIR 45

#define GRID2    (148 * 8)               // 1184 blocks, 8 CTA/SM, all resident
#define NTHREADS 256
#define OUT_F4   (NB * CC * 400)         // 3276800 float4 outputs

// scratch (no cudaMalloc allowed)
__device__ float g_xt[NB * CC * LL * VV];     // [n][c][l][v]
__device__ float g_s[NB * C4 * LL];           // [n][o][l]
__device__ float g_gate[NB * CC * LL];        // [n][c][l]

// self-resetting grid barrier state (zero-init; g_go flips each use,
// g_cnt returns to 0 -> consistent across graph replays)
__device__ int g_cnt[4];
__device__ volatile int g_go[4];

__constant__ int c_pv[NPAIR] = {
    1,0,20,
    0,20,12,16,2,4,8,
    12,16,2,4,8,13,17,3,5,9,
    13,17,3,5,9,14,18,6,10,
    14,18,6,10,15,19,7,11,
    15,19,7,11,21,22,23,24};
__constant__ int c_off[LL + 1] = {0,3,10,20,29,37,45};
__constant__ float c_inv_cnt[LL] = {1.f/3.f, 1.f/7.f, 1.f/10.f, 1.f/9.f, 1.f/8.f, 1.f/8.f};

__device__ __forceinline__ void grid_barrier(int i) {
    __syncthreads();
    if (threadIdx.x == 0) {
        __threadfence();                      // publish this block's stores
        const int sense = g_go[i];            // read BEFORE arriving
        const int a = atomicAdd(&g_cnt[i], 1);
        if (a == GRID2 - 1) {
            g_cnt[i] = 0;
            __threadfence();
            g_go[i] = 1 - sense;
        } else {
            while (g_go[i] == sense) { __nanosleep(64); }
            __threadfence();                  // acquire peers' stores
        }
    }
    __syncthreads();
}

// ---------------------------------------------------------------------------
// Kernel 1 (R3-proven, ~49us @ 83% DRAM): x_t[n,c,l,v] = max_t x[n,c,l,t,v]
// ---------------------------------------------------------------------------
__global__ __launch_bounds__(128) void k_tmax(const float* __restrict__ x) {
    __shared__ float4 tile4[400];
    float* tile = reinterpret_cast<float*>(tile4);
    const int b = blockIdx.x;                 // (n*C + c)*L + l
    const float4* xb = reinterpret_cast<const float4*>(x) + (size_t)b * 400;
    const int tid = threadIdx.x;
    #pragma unroll
    for (int i = 0; i < 3; i++) tile4[tid + i * 128] = xb[tid + i * 128];
    if (tid < 16) tile4[tid + 384] = xb[tid + 384];
    __syncthreads();
    if (tid < VV) {
        float m = tile[tid];
        #pragma unroll
        for (int t = 1; t < TT; t++) m = fmaxf(m, tile[t * VV + tid]);
        g_xt[(size_t)b * VV + tid] = m;
    }
}

// ---------------------------------------------------------------------------
// Kernel 2: persistent, fully occupied (8 CTA/SM, <=32 regs).
//   Phase A (blocks 0..191): s-projection for one (n,l) unit each.
//   barrier
//   Phase B (blocks 0..31):  Gram / top-3 / EdgeConv / agg / sigmoid gate.
//   barrier
//   Phase C (all blocks):    gated sum over L, grid-strided float4.
// ---------------------------------------------------------------------------
__global__ __launch_bounds__(NTHREADS, 8) void k_rest(
    const float* __restrict__ x,
    const float* __restrict__ W_down, const float* __restrict__ b_down,
    const float* __restrict__ g_down, const float* __restrict__ be_down,
    const float* __restrict__ m_down, const float* __restrict__ v_down,
    const float* __restrict__ W_edge, const float* __restrict__ g_edge,
    const float* __restrict__ be_edge, const float* __restrict__ m_edge,
    const float* __restrict__ v_edge, const float* __restrict__ W_agg,
    const float* __restrict__ b_agg, float* __restrict__ out) {
    const int t = threadIdx.x;
    const int o = t & 63;
    const int g = t >> 6;

    __shared__ float shX[10 * 256];           // gathered X rows
    __shared__ float parts[4 * 10 * 64];      // [g][p][o] partial dots
    __shared__ float sh_s[C4][LL];
    __shared__ float sh_G[LL * LL];
    __shared__ int   sh_idx[LL][3];
    __shared__ float sh_e[C4][LL];

    // ==== Phase A: s[n][o][l] (one unit per block, blocks < 192) ====
    if (blockIdx.x < NB * LL) {
        const int n = blockIdx.x / LL;
        const int l = blockIdx.x % LL;
        const int p0 = c_off[l];
        const int cnt = c_off[l + 1] - p0;
        const float* xb = g_xt + ((size_t)n * CC * LL + l) * VV;
        for (int i = t; i < cnt * 256; i += 256) {
            const int p = i >> 8, c = i & 255;
            shX[p * 256 + c] = xb[(size_t)c * (LL * VV) + c_pv[p0 + p]];
        }
        __syncthreads();

        // thread (o, g): p outer, scalar acc (keeps regs <= 32)
        const float4* wr = reinterpret_cast<const float4*>(W_down) + o * 64 + g * 16;
        for (int p = 0; p < cnt; p++) {
            const float4* xp = reinterpret_cast<const float4*>(shX + p * 256 + g * 64);
            float a = 0.f;
            #pragma unroll
            for (int i = 0; i < 16; i++) {
                const float4 w = wr[i];       // L1-resident after p=0
                const float4 xv = xp[i];
                a += w.x * xv.x + w.y * xv.y + w.z * xv.z + w.w * xv.w;
            }
            parts[(g * 10 + p) * 64 + o] = a;
        }
        __syncthreads();

        if (t < 64) {
            const float gs  = g_down[t] * rsqrtf(v_down[t] + EPS);
            const float shb = be_down[t] - m_down[t] * gs;
            const float bd  = b_down[t];
            float ssum = 0.f;
            for (int p = 0; p < cnt; p++) {
                const float y = (parts[p * 64 + t] + parts[(10 + p) * 64 + t] +
                                 parts[(20 + p) * 64 + t] + parts[(30 + p) * 64 + t]
                                 + bd) * gs + shb;
                ssum += fmaxf(y, 0.f);
            }
            g_s[((size_t)n * C4 + t) * LL + l] = ssum * c_inv_cnt[l];
        }
    }
    grid_barrier(0);

    // ==== Phase B: knn + EdgeConv + gate, blocks 0..31 ====
    if (blockIdx.x < NB) {
        const int n = blockIdx.x;
        for (int i = t; i < C4 * LL; i += 256)
            sh_s[i / LL][i % LL] = g_s[(size_t)n * C4 * LL + i];
        __syncthreads();

        if (t < LL * LL) {
            const int i = t / LL, j = t % LL;
            float acc = 0.f;
            #pragma unroll 8
            for (int c = 0; c < C4; c++) acc += sh_s[c][i] * sh_s[c][j];
            sh_G[t] = acc;
        }
        __syncthreads();

        if (t < LL) {
            float d[LL];
            bool used[LL];
            const float sqi = sh_G[t * LL + t];
            #pragma unroll
            for (int j = 0; j < LL; j++) {
                d[j] = 2.f * sh_G[t * LL + j] - sqi - sh_G[j * LL + j];
                used[j] = false;
            }
            #pragma unroll
            for (int k = 0; k < 3; k++) {
                float best = -INFINITY; int bi = 0;
                #pragma unroll
                for (int j = 0; j < LL; j++)
                    if (!used[j] && d[j] > best) { best = d[j]; bi = j; }
                used[bi] = true;
                sh_idx[t][k] = bi;
            }
        }
        __syncthreads();

        // EdgeConv: weights via float4 from global (L2-hit across 32 blocks)
        for (int item = t; item < LL * C4; item += 256) {
            const int oo = item & 63;
            const int l  = item >> 6;
            const float4* w14 = reinterpret_cast<const float4*>(W_edge + oo * 128);
            const int n0 = sh_idx[l][0], n1 = sh_idx[l][1], n2 = sh_idx[l][2];
            float base = 0.f, a0 = 0.f, a1 = 0.f, a2 = 0.f;
            #pragma unroll 4
            for (int i = 0; i < 16; i++) {
                const float4 w = w14[i];
                const float4 w2 = w14[16 + i];
                const int c = 4 * i;
                #pragma unroll
                for (int q = 0; q < 4; q++) {
                    const float wq = (&w.x)[q];
                    base += ((&w2.x)[q] - wq) * sh_s[c + q][l];
                    a0 += wq * sh_s[c + q][n0];
                    a1 += wq * sh_s[c + q][n1];
                    a2 += wq * sh_s[c + q][n2];
                }
            }
            const float gs  = g_edge[oo] * rsqrtf(v_edge[oo] + EPS);
            const float shb = be_edge[oo] - m_edge[oo] * gs;
            float m = -INFINITY;
            float ys[3] = {a0 + base, a1 + base, a2 + base};
            #pragma unroll
            for (int k = 0; k < 3; k++) {
                float y = ys[k] * gs + shb;
                y = fmaxf(y, 0.f) + SLOPE * fminf(y, 0.f);
                m = fmaxf(m, y);
            }
            sh_e[oo][l] = m;
        }
        __syncthreads();

        {
            const int oc = t;
            float a[LL];
            const float bb = b_agg[oc];
            #pragma unroll
            for (int l = 0; l < LL; l++) a[l] = bb;
            const float4* wr = reinterpret_cast<const float4*>(W_agg + oc * C4);
            #pragma unroll 4
            for (int i = 0; i < 16; i++) {
                const float4 w = wr[i];
                const int c = 4 * i;
                #pragma unroll
                for (int l = 0; l < LL; l++)
                    a[l] += w.x * sh_e[c][l] + w.y * sh_e[c+1][l]
                          + w.z * sh_e[c+2][l] + w.w * sh_e[c+3][l];
            }
            float* gp = g_gate + ((size_t)n * CC + oc) * LL;
            #pragma unroll
            for (int l = 0; l < LL; l++)
                gp[l] = 1.f / (1.f + expf(-a[l]));
        }
    }
    grid_barrier(1);

    // ==== Phase C: gated sum over L (grid-stride, float4) ====
    {
        const float4* x4 = reinterpret_cast<const float4*>(x);
        float4* out4 = reinterpret_cast<float4*>(out);
        const int stride = GRID2 * NTHREADS;
        for (int idx = blockIdx.x * NTHREADS + t; idx < OUT_F4; idx += stride) {
            const int tv4 = idx % 400;
            const int nc  = idx / 400;
            const float4* xb = x4 + (size_t)nc * (LL * 400) + tv4;
            const float* gp = g_gate + (size_t)nc * LL;
            float4 acc = make_float4(0.f, 0.f, 0.f, 0.f);
            #pragma unroll
            for (int l = 0; l < LL; l++) {
                const float gv = gp[l];
                const float4 xv = xb[l * 400];
                acc.x += xv.x * gv; acc.y += xv.y * gv;
                acc.z += xv.z * gv; acc.w += xv.w * gv;
            }
            out4[idx] = acc;
        }
    }
}

// ---------------------------------------------------------------------------
extern "C" void kernel_launch(void* const* d_in, const int* in_sizes, int n_in,
                              void* d_out, int out_size) {
    const float* x       = (const float*)d_in[0];
    const float* W_down  = (const float*)d_in[1];
    const float* b_down  = (const float*)d_in[2];
    const float* g_down  = (const float*)d_in[3];
    const float* be_down = (const float*)d_in[4];
    const float* m_down  = (const float*)d_in[5];
    const float* v_down  = (const float*)d_in[6];
    const float* W_edge  = (const float*)d_in[7];
    const float* g_edge  = (const float*)d_in[8];
    const float* be_edge = (const float*)d_in[9];
    const float* m_edge  = (const float*)d_in[10];
    const float* v_edge  = (const float*)d_in[11];
    const float* W_agg   = (const float*)d_in[12];
    const float* b_agg   = (const float*)d_in[13];
    float* out = (float*)d_out;

    k_tmax<<<NB * CC * LL, 128>>>(x);
    k_rest<<<GRID2, NTHREADS>>>(
        x, W_down, b_down, g_down, be_down, m_down, v_down,
        W_edge, g_edge, be_edge, m_edge, v_edge, W_agg, b_agg, out);
}

// round 15
// speedup vs baseline: 1.2002x; 1.1394x over previous
#include <cuda_runtime.h>
#include <math.h>
#include <stdint.h>

#define NB   32
#define CC   256
#define C4   64
#define LL   6
#define TT   64
#define VV   25
#define EPS  1e-5f
#define SLOPE 0.2f
#define NPAIR 45

// scratch (no cudaMalloc allowed)
__device__ float g_xt[NB * CC * LL * VV];     // [n][c][l][v]
__device__ float g_gate[NB * CC * LL];        // [n][c][l]

// flattened (layer, joint) pairs for the hierarchy means
__constant__ int c_pv[NPAIR] = {
    1,0,20,
    0,20,12,16,2,4,8,
    12,16,2,4,8,13,17,3,5,9,
    13,17,3,5,9,14,18,6,10,
    14,18,6,10,15,19,7,11,
    15,19,7,11,21,22,23,24};
__constant__ int c_pl[NPAIR] = {
    0,0,0,
    1,1,1,1,1,1,1,
    2,2,2,2,2,2,2,2,2,2,
    3,3,3,3,3,3,3,3,3,
    4,4,4,4,4,4,4,4,
    5,5,5,5,5,5,5,5};
__constant__ int c_off[LL + 1] = {0,3,10,20,29,37,45};
__constant__ float c_inv_cnt[LL] = {1.f/3.f, 1.f/7.f, 1.f/10.f, 1.f/9.f, 1.f/8.f, 1.f/8.f};

// dynamic smem layout for k_smid (floats)
#define SMX_X     0                        // shX  [45][256]
#define SMX_WE    (SMX_X + NPAIR * 256)    // shWe [64][129]
#define SMX_PARTS (SMX_WE + 64 * 129)      // parts[4][10][64]
#define SMX_S     (SMX_PARTS + 4 * 10 * 64)// sh_s [64][6]
#define SMX_G     (SMX_S + C4 * LL)        // sh_G [36]
#define SMX_E     (SMX_G + 36)             // sh_e [64][6]
#define SMX_IDX   (SMX_E + C4 * LL)        // sh_idx [18] (as float-slots)
#define SMID_FLOATS (SMX_IDX + 18)
#define SMID_BYTES  (SMID_FLOATS * 4)

__device__ __forceinline__ void cp_async4(void* dst_smem, const void* src) {
    uint32_t d = (uint32_t)__cvta_generic_to_shared(dst_smem);
    asm volatile("cp.async.ca.shared.global [%0], [%1], 4;\n" :: "r"(d), "l"(src));
}
__device__ __forceinline__ void cp_wait_all_f() {
    asm volatile("cp.async.wait_all;\n" ::: "memory");
}

// ---------------------------------------------------------------------------
// Kernel 1 (measured 48.7us @ 83.5% DRAM): x_t[n,c,l,v] = max_t x[n,c,l,t,v]
// ---------------------------------------------------------------------------
__global__ __launch_bounds__(128) void k_tmax(const float* __restrict__ x) {
    __shared__ float4 tile4[400];
    float* tile = reinterpret_cast<float*>(tile4);
    const int b = blockIdx.x;                 // (n*C + c)*L + l
    const float4* xb = reinterpret_cast<const float4*>(x) + (size_t)b * 400;
    const int tid = threadIdx.x;
    #pragma unroll
    for (int i = 0; i < 3; i++) tile4[tid + i * 128] = xb[tid + i * 128];
    if (tid < 16) tile4[tid + 384] = xb[tid + 384];
    __syncthreads();
    if (tid < VV) {
        float m = tile[tid];
        #pragma unroll
        for (int t = 1; t < TT; t++) m = fmaxf(m, tile[t * VV + tid]);
        g_xt[(size_t)b * VV + tid] = m;
    }
}

// ---------------------------------------------------------------------------
// Kernel 2: whole middle per sample. One block per n, 256 threads.
// All 45x256 x_t gathers issued upfront via cp.async (full MLP, one latency).
// ---------------------------------------------------------------------------
__global__ __launch_bounds__(256) void k_smid(
    const float* __restrict__ W_down, const float* __restrict__ b_down,
    const float* __restrict__ g_down, const float* __restrict__ be_down,
    const float* __restrict__ m_down, const float* __restrict__ v_down,
    const float* __restrict__ W_edge, const float* __restrict__ g_edge,
    const float* __restrict__ be_edge, const float* __restrict__ m_edge,
    const float* __restrict__ v_edge, const float* __restrict__ W_agg,
    const float* __restrict__ b_agg) {
    extern __shared__ float sm[];
    float* shX   = sm + SMX_X;
    float* shWe  = sm + SMX_WE;
    float* parts = sm + SMX_PARTS;
    float* sh_s  = sm + SMX_S;                // [c][l] : c*LL + l
    float* sh_G  = sm + SMX_G;
    float* sh_e  = sm + SMX_E;                // [o][l] : o*LL + l
    int*   sh_idx = reinterpret_cast<int*>(sm + SMX_IDX);  // [l][k]

    const int n = blockIdx.x;
    const int t = threadIdx.x;
    const int o = t & 63;
    const int g = t >> 6;

    // ---- Upfront gather: all 45 pairs, channel c = t (fully unrolled) ----
    {
        const float* xb = g_xt + ((size_t)(n * CC) + t) * (LL * VV);
        #pragma unroll
        for (int p = 0; p < NPAIR; p++) {
            const int off = c_pl[p] * VV + c_pv[p];   // compile-time constant
            cp_async4(&shX[p * 256 + t], xb + off);
        }
    }

    // stage W_edge into smem (coalesced float4, stride pad 129)
    for (int i = t; i < 64 * 32; i += 256) {
        const int r = i >> 5, c4 = i & 31;
        const float4 w = reinterpret_cast<const float4*>(W_edge + r * 128)[c4];
        float* d = &shWe[r * 129 + c4 * 4];
        d[0] = w.x; d[1] = w.y; d[2] = w.z; d[3] = w.w;
    }

    // W_down segment -> registers (row o, quarter g)
    float wreg[64];
    {
        const float4* wr = reinterpret_cast<const float4*>(W_down + o * CC + g * 64);
        #pragma unroll
        for (int i = 0; i < 16; i++) {
            const float4 w = wr[i];
            wreg[4*i] = w.x; wreg[4*i+1] = w.y; wreg[4*i+2] = w.z; wreg[4*i+3] = w.w;
        }
    }

    cp_wait_all_f();
    __syncthreads();

    // ---- Stage 1: s for all 6 layers (data in smem) ----
    for (int l = 0; l < LL; l++) {
        const int p0 = c_off[l];
        const int cnt = c_off[l + 1] - p0;

        float acc[10];
        #pragma unroll
        for (int p = 0; p < 10; p++) acc[p] = 0.f;
        #pragma unroll
        for (int p = 0; p < 10; p++) {
            if (p < cnt) {
                const float4* xp = reinterpret_cast<const float4*>(
                    shX + (p0 + p) * 256 + g * 64);
                float a = 0.f;
                #pragma unroll
                for (int i = 0; i < 16; i++) {
                    const float4 xv = xp[i];
                    a += wreg[4*i] * xv.x + wreg[4*i+1] * xv.y
                       + wreg[4*i+2] * xv.z + wreg[4*i+3] * xv.w;
                }
                acc[p] = a;
            }
        }
        __syncthreads();                      // parts reuse across layers
        #pragma unroll
        for (int p = 0; p < 10; p++)
            if (p < cnt) parts[(g * 10 + p) * 64 + o] = acc[p];
        __syncthreads();

        if (t < 64) {
            const float gs  = g_down[t] * rsqrtf(v_down[t] + EPS);
            const float shb = be_down[t] - m_down[t] * gs;
            const float bd  = b_down[t];
            float ssum = 0.f;
            #pragma unroll
            for (int p = 0; p < 10; p++) {
                if (p < cnt) {
                    const float y = (parts[p * 64 + t] + parts[(10 + p) * 64 + t] +
                                     parts[(20 + p) * 64 + t] + parts[(30 + p) * 64 + t]
                                     + bd) * gs + shb;
                    ssum += fmaxf(y, 0.f);
                }
            }
            sh_s[t * LL + l] = ssum * c_inv_cnt[l];
        }
    }
    __syncthreads();

    // ---- Stage 2a: Gram matrix ----
    if (t < LL * LL) {
        const int i = t / LL, j = t % LL;
        float acc = 0.f;
        #pragma unroll 8
        for (int c = 0; c < C4; c++) acc += sh_s[c * LL + i] * sh_s[c * LL + j];
        sh_G[t] = acc;
    }
    __syncthreads();

    // ---- Stage 2b: top-3 neighbors (stable tie-break matching lax.top_k) ----
    if (t < LL) {
        float d[LL];
        bool used[LL];
        const float sqi = sh_G[t * LL + t];
        #pragma unroll
        for (int j = 0; j < LL; j++) {
            d[j] = 2.f * sh_G[t * LL + j] - sqi - sh_G[j * LL + j];
            used[j] = false;
        }
        #pragma unroll
        for (int k = 0; k < 3; k++) {
            float best = -INFINITY; int bi = 0;
            #pragma unroll
            for (int j = 0; j < LL; j++)
                if (!used[j] && d[j] > best) { best = d[j]; bi = j; }
            used[bi] = true;
            sh_idx[t * 3 + k] = bi;
        }
    }
    __syncthreads();

    // ---- Stage 2c: EdgeConv + BN + leaky + max over k ----
    for (int item = t; item < LL * C4; item += 256) {
        const int oo = item & 63;
        const int l  = item >> 6;
        const float* w1 = &shWe[oo * 129];
        const float* w2 = w1 + 64;
        const int n0 = sh_idx[l * 3], n1 = sh_idx[l * 3 + 1], n2 = sh_idx[l * 3 + 2];
        float base = 0.f, a0 = 0.f, a1 = 0.f, a2 = 0.f;
        #pragma unroll 8
        for (int c = 0; c < C4; c++) {
            const float w = w1[c];
            base += (w2[c] - w) * sh_s[c * LL + l];
            a0 += w * sh_s[c * LL + n0];
            a1 += w * sh_s[c * LL + n1];
            a2 += w * sh_s[c * LL + n2];
        }
        const float gs  = g_edge[oo] * rsqrtf(v_edge[oo] + EPS);
        const float shb = be_edge[oo] - m_edge[oo] * gs;
        float m = -INFINITY;
        float ys[3] = {a0 + base, a1 + base, a2 + base};
        #pragma unroll
        for (int k = 0; k < 3; k++) {
            float y = ys[k] * gs + shb;
            y = fmaxf(y, 0.f) + SLOPE * fminf(y, 0.f);
            m = fmaxf(m, y);
        }
        sh_e[oo * LL + l] = m;
    }
    __syncthreads();

    // ---- Stage 2d: att = W_agg @ e + b_agg ; gate = sigmoid ----
    {
        const int oc = t;                      // 256 threads == C outputs
        float a[LL];
        const float bb = b_agg[oc];
        #pragma unroll
        for (int l = 0; l < LL; l++) a[l] = bb;
        const float4* wr = reinterpret_cast<const float4*>(W_agg + oc * C4);
        #pragma unroll
        for (int i = 0; i < 16; i++) {
            const float4 w = wr[i];
            const int c = 4 * i;
            #pragma unroll
            for (int l = 0; l < LL; l++)
                a[l] += w.x * sh_e[c * LL + l] + w.y * sh_e[(c+1) * LL + l]
                      + w.z * sh_e[(c+2) * LL + l] + w.w * sh_e[(c+3) * LL + l];
        }
        float* gp = g_gate + ((size_t)n * CC + oc) * LL;
        #pragma unroll
        for (int l = 0; l < LL; l++)
            gp[l] = 1.f / (1.f + expf(-a[l]));
    }
}

// ---------------------------------------------------------------------------
// Kernel 3 (measured 53.2us @ 84.3% DRAM): out = sum_l x * gate   (float4)
// ---------------------------------------------------------------------------
__global__ __launch_bounds__(256) void k_gatesum(const float* __restrict__ x,
                                                 float* __restrict__ out) {
    const int gid = blockIdx.x * 256 + threadIdx.x;     // [0, 32*256*400)
    const int tv4 = gid % 400;
    const int nc  = gid / 400;
    const float4* xb = reinterpret_cast<const float4*>(x) + (size_t)nc * (LL * 400) + tv4;
    const float* gp = g_gate + (size_t)nc * LL;
    float4 acc = make_float4(0.f, 0.f, 0.f, 0.f);
    #pragma unroll
    for (int l = 0; l < LL; l++) {
        const float g = gp[l];
        const float4 xv = xb[l * 400];
        acc.x += xv.x * g; acc.y += xv.y * g;
        acc.z += xv.z * g; acc.w += xv.w * g;
    }
    reinterpret_cast<float4*>(out)[(size_t)nc * 400 + tv4] = acc;
}

// ---------------------------------------------------------------------------
extern "C" void kernel_launch(void* const* d_in, const int* in_sizes, int n_in,
                              void* d_out, int out_size) {
    const float* x       = (const float*)d_in[0];
    const float* W_down  = (const float*)d_in[1];
    const float* b_down  = (const float*)d_in[2];
    const float* g_down  = (const float*)d_in[3];
    const float* be_down = (const float*)d_in[4];
    const float* m_down  = (const float*)d_in[5];
    const float* v_down  = (const float*)d_in[6];
    const float* W_edge  = (const float*)d_in[7];
    const float* g_edge  = (const float*)d_in[8];
    const float* be_edge = (const float*)d_in[9];
    const float* m_edge  = (const float*)d_in[10];
    const float* v_edge  = (const float*)d_in[11];
    const float* W_agg   = (const float*)d_in[12];
    const float* b_agg   = (const float*)d_in[13];
    float* out = (float*)d_out;

    (void)cudaFuncSetAttribute(k_smid,
                               cudaFuncAttributeMaxDynamicSharedMemorySize,
                               SMID_BYTES);
    k_tmax<<<NB * CC * LL, 128>>>(x);
    k_smid<<<NB, 256, SMID_BYTES>>>(W_down, b_down, g_down, be_down, m_down,
                                    v_down, W_edge, g_edge, be_edge, m_edge,
                                    v_edge, W_agg, b_agg);
    k_gatesum<<<(NB * CC * 400) / 256, 256>>>(x, out);
}